// round 5
// baseline (speedup 1.0000x reference)
#include <cuda_runtime.h>
#include <math.h>

#define BV   8
#define CCH  47
#define CP   48          // padded channels (192B per pixel, sector-aligned)
#define FHH  60
#define FWW  80
#define DHH  240
#define DWW  320
#define NPTS 150000

// Scratch (no allocations allowed): transposed feats + per-view projection data.
// g_proj[v] = { ip[3][4] (12), Kc row0 (3), Kc row1 (3), Kd row0 (3), Kd row1 (3) } = 24
__device__ float g_proj[BV][24];
__device__ __align__(16) float g_feats_t[BV * FHH * FWW * CP];

// ---------------------------------------------------------------------------
// Kernel 1: invert 8 poses (Gauss-Jordan, double — exact for these poses) and
// stash inv rows + K rows UNfused so per-point math can mirror the reference.
// ---------------------------------------------------------------------------
__global__ void prep_proj_kernel(const float* __restrict__ poses,
                                 const float* __restrict__ Kc,
                                 const float* __restrict__ Kd) {
    int v = threadIdx.x;
    if (v >= BV) return;

    double a[4][8];
    for (int i = 0; i < 4; i++)
        for (int j = 0; j < 4; j++) {
            a[i][j]     = (double)poses[v * 16 + i * 4 + j];
            a[i][4 + j] = (i == j) ? 1.0 : 0.0;
        }
    for (int col = 0; col < 4; col++) {
        int piv = col;
        double best = fabs(a[col][col]);
        for (int r = col + 1; r < 4; r++) {
            double m = fabs(a[r][col]);
            if (m > best) { best = m; piv = r; }
        }
        if (piv != col)
            for (int j = 0; j < 8; j++) {
                double t = a[col][j]; a[col][j] = a[piv][j]; a[piv][j] = t;
            }
        double inv = 1.0 / a[col][col];
        for (int j = 0; j < 8; j++) a[col][j] *= inv;
        for (int r = 0; r < 4; r++) {
            if (r == col) continue;
            double f = a[r][col];
            for (int j = 0; j < 8; j++) a[r][j] -= f * a[col][j];
        }
    }
    float* o = g_proj[v];
    for (int i = 0; i < 3; i++)
        for (int j = 0; j < 4; j++)
            o[i * 4 + j] = (float)a[i][4 + j];
    for (int j = 0; j < 3; j++) o[12 + j] = Kc[v * 9 + 0 + j];   // Kc row 0
    for (int j = 0; j < 3; j++) o[15 + j] = Kc[v * 9 + 3 + j];   // Kc row 1
    for (int j = 0; j < 3; j++) o[18 + j] = Kd[v * 9 + 0 + j];   // Kd row 0
    for (int j = 0; j < 3; j++) o[21 + j] = Kd[v * 9 + 3 + j];   // Kd row 1
}

// ---------------------------------------------------------------------------
// Kernel 2: transpose (V,C,H,W) -> (V,H,W,Cpad): a pixel's 47 channels become
// 188 contiguous bytes (6 L2 sectors instead of 47).
// ---------------------------------------------------------------------------
__global__ void transpose_feats_kernel(const float* __restrict__ feats) {
    int idx = blockIdx.x * blockDim.x + threadIdx.x;
    const int total = BV * FHH * FWW * CP;
    if (idx >= total) return;
    int c = idx % CP;
    int p = idx / CP;              // v*FH*FW + y*FW + x
    int x = p % FWW;
    int t = p / FWW;
    int y = t % FHH;
    int v = t / FHH;
    float val = 0.0f;
    if (c < CCH)
        val = feats[((v * CCH + c) * FHH + y) * FWW + x];
    g_feats_t[idx] = val;
}

// Unfused multiply-then-reduce dot (XLA loop-fusion lowering of a tiny dot):
// every product individually rounded, then rounded adds. With the zero
// structure of inv_pose / K this is order-independent.
__device__ __forceinline__ float dot4_mr(const float* r, float x, float y,
                                         float z, float w) {
    float t0 = __fmul_rn(r[0], x);
    float t1 = __fmul_rn(r[1], y);
    float t2 = __fmul_rn(r[2], z);
    float t3 = __fmul_rn(r[3], w);
    return __fadd_rn(__fadd_rn(__fadd_rn(t0, t1), t2), t3);
}
__device__ __forceinline__ float dot3_mr(const float* r, float x, float y,
                                         float z) {
    float t0 = __fmul_rn(r[0], x);
    float t1 = __fmul_rn(r[1], y);
    float t2 = __fmul_rn(r[2], z);
    return __fadd_rn(__fadd_rn(t0, t1), t2);
}

// ---------------------------------------------------------------------------
// Kernel 3: main fused projection + sampling + accumulation. 1 thread/point.
// ---------------------------------------------------------------------------
__global__ void __launch_bounds__(128)
fuse_kernel(const float* __restrict__ coords,
            const float* __restrict__ depth,
            float* __restrict__ out) {
    int n = blockIdx.x * blockDim.x + threadIdx.x;
    if (n >= NPTS) return;

    const float px = coords[n * 3 + 0];
    const float py = coords[n * 3 + 1];
    const float pz = coords[n * 3 + 2];

    float acc[CP];
#pragma unroll
    for (int c = 0; c < CP; c++) acc[c] = 0.0f;
    float wsum = 0.0f, cnt = 0.0f;

#pragma unroll 1
    for (int v = 0; v < BV; v++) {
        const float* P = g_proj[v];
        // cam = inv_pose[:3,:] @ [p,1]  (reference's first einsum; exact here)
        float cam0 = dot4_mr(P + 0, px, py, pz, 1.0f);
        float cam1 = dot4_mr(P + 4, px, py, pz, 1.0f);
        float cam2 = dot4_mr(P + 8, px, py, pz, 1.0f);

        // uvw = K @ cam (rows 0,1); K row 2 = [0,0,1] -> uvw2 == cam2 exactly
        float z  = cam2;
        float zs = (fabsf(z) > 1e-6f) ? z : 1e-6f;

        // XLA simplifier rewrites  X / broadcast(Y)  ->  X * broadcast(1/Y):
        // one correctly-rounded reciprocal, then individually rounded products.
        float recip = __fdiv_rn(1.0f, zs);

        float uc = __fmul_rn(dot3_mr(P + 12, cam0, cam1, cam2), recip);
        float vc = __fmul_rn(dot3_mr(P + 15, cam0, cam1, cam2), recip);
        float ud = __fmul_rn(dot3_mr(P + 18, cam0, cam1, cam2), recip);
        float vd = __fmul_rn(dot3_mr(P + 21, cam0, cam1, cam2), recip);

        bool valid_c = (uc >= 0.0f) & (uc <= (float)(FWW - 1)) &
                       (vc >= 0.0f) & (vc <= (float)(FHH - 1));
        bool valid_d = (ud >= 0.0f) & (ud <= (float)(DWW - 1)) &
                       (vd >= 0.0f) & (vd <= (float)(DHH - 1));

        // nearest depth sample (rintf == round-half-to-even == jnp.round)
        int xi = (int)fminf(fmaxf(rintf(ud), 0.0f), (float)(DWW - 1));
        int yi = (int)fminf(fmaxf(rintf(vd), 0.0f), (float)(DHH - 1));
        float ds = __ldg(&depth[(v * DHH + yi) * DWW + xi]);

        bool valid = valid_c & valid_d & (z > 0.0f) & (ds > 0.0f);
        float dist = __fmul_rn(fabsf(__fsub_rn(z, ds)), 16.0f);
        float w = valid ? expf(-__fmul_rn(dist, dist)) : 0.0f;
        wsum += w;
        cnt  += valid ? 1.0f : 0.0f;

        if (w != 0.0f) {
            float ucl = fminf(fmaxf(uc, 0.0f), (float)(FWW - 1));
            float vcl = fminf(fmaxf(vc, 0.0f), (float)(FHH - 1));
            float x0f = floorf(ucl), y0f = floorf(vcl);
            int x0 = (int)x0f, y0 = (int)y0f;
            int x1 = min(x0 + 1, FWW - 1);
            int y1 = min(y0 + 1, FHH - 1);
            float wx = ucl - x0f, wy = vcl - y0f;
            float w00 = w * (1.0f - wy) * (1.0f - wx);
            float w01 = w * (1.0f - wy) * wx;
            float w10 = w * wy * (1.0f - wx);
            float w11 = w * wy * wx;

            const int base = v * FHH * FWW;
            const float4* q00 = (const float4*)&g_feats_t[(base + y0 * FWW + x0) * CP];
            const float4* q01 = (const float4*)&g_feats_t[(base + y0 * FWW + x1) * CP];
            const float4* q10 = (const float4*)&g_feats_t[(base + y1 * FWW + x0) * CP];
            const float4* q11 = (const float4*)&g_feats_t[(base + y1 * FWW + x1) * CP];
#pragma unroll
            for (int c4 = 0; c4 < CP / 4; c4++) {
                float4 a = __ldg(&q00[c4]);
                float4 b = __ldg(&q01[c4]);
                float4 cc = __ldg(&q10[c4]);
                float4 d = __ldg(&q11[c4]);
                acc[4 * c4 + 0] += w00 * a.x + w01 * b.x + w10 * cc.x + w11 * d.x;
                acc[4 * c4 + 1] += w00 * a.y + w01 * b.y + w10 * cc.y + w11 * d.y;
                acc[4 * c4 + 2] += w00 * a.z + w01 * b.z + w10 * cc.z + w11 * d.z;
                acc[4 * c4 + 3] += w00 * a.w + w01 * b.w + w10 * cc.w + w11 * d.w;
            }
        }
    }

    // density (C,N) then weight_sum (N) then count (N)
#pragma unroll
    for (int c = 0; c < CCH; c++) out[c * NPTS + n] = acc[c];
    out[CCH * NPTS + n]         = wsum;
    out[CCH * NPTS + NPTS + n]  = cnt;
}

// ---------------------------------------------------------------------------
extern "C" void kernel_launch(void* const* d_in, const int* in_sizes, int n_in,
                              void* d_out, int out_size) {
    const float* img_feats  = (const float*)d_in[0];   // (1,8,47,60,80)
    const float* pred_depth = (const float*)d_in[1];   // (1,8,240,320)
    const float* poses      = (const float*)d_in[2];   // (1,8,4,4)
    const float* K_color    = (const float*)d_in[3];   // (1,8,3,3)
    const float* K_depth    = (const float*)d_in[4];   // (1,8,3,3)
    const float* coords     = (const float*)d_in[5];   // (1,150000,3)
    float* out = (float*)d_out;

    prep_proj_kernel<<<1, 32>>>(poses, K_color, K_depth);

    const int tot = BV * FHH * FWW * CP;
    transpose_feats_kernel<<<(tot + 255) / 256, 256>>>(img_feats);

    fuse_kernel<<<(NPTS + 127) / 128, 128>>>(coords, pred_depth, out);
}

// round 6
// speedup vs baseline: 1.1908x; 1.1908x over previous
#include <cuda_runtime.h>
#include <math.h>

#define BV   8
#define CCH  47
#define CP   48          // padded channels (192B per pixel)
#define FHH  60
#define FWW  80
#define DHH  240
#define DWW  320
#define NPTS 150000
#define WPB  8           // warps (points) per block in fuse

// Scratch (no allocations allowed)
__device__ float g_proj[BV][24];
__device__ __align__(16) float g_feats_t[BV * FHH * FWW * CP];

// ---------------------------------------------------------------------------
// Float Gauss-Jordan pose inverse (exact for these I+translation poses, and
// identical to the reference's f32 inverse) + stash K rows unfused.
// ---------------------------------------------------------------------------
__device__ void prep_view(int v, const float* __restrict__ poses,
                          const float* __restrict__ Kc,
                          const float* __restrict__ Kd) {
    float a[4][8];
    for (int i = 0; i < 4; i++)
        for (int j = 0; j < 4; j++) {
            a[i][j]     = poses[v * 16 + i * 4 + j];
            a[i][4 + j] = (i == j) ? 1.0f : 0.0f;
        }
    for (int col = 0; col < 4; col++) {
        int piv = col;
        float best = fabsf(a[col][col]);
        for (int r = col + 1; r < 4; r++) {
            float m = fabsf(a[r][col]);
            if (m > best) { best = m; piv = r; }
        }
        if (piv != col)
            for (int j = 0; j < 8; j++) {
                float t = a[col][j]; a[col][j] = a[piv][j]; a[piv][j] = t;
            }
        float inv = 1.0f / a[col][col];
        for (int j = 0; j < 8; j++) a[col][j] *= inv;
        for (int r = 0; r < 4; r++) {
            if (r == col) continue;
            float f = a[r][col];
            for (int j = 0; j < 8; j++) a[r][j] -= f * a[col][j];
        }
    }
    float* o = g_proj[v];
    for (int i = 0; i < 3; i++)
        for (int j = 0; j < 4; j++)
            o[i * 4 + j] = a[i][4 + j];
    for (int j = 0; j < 3; j++) o[12 + j] = Kc[v * 9 + 0 + j];
    for (int j = 0; j < 3; j++) o[15 + j] = Kc[v * 9 + 3 + j];
    for (int j = 0; j < 3; j++) o[18 + j] = Kd[v * 9 + 0 + j];
    for (int j = 0; j < 3; j++) o[21 + j] = Kd[v * 9 + 3 + j];
}

// ---------------------------------------------------------------------------
// Transpose (V,C,H,W) -> (V,H,W,Cpad) via smem, fully coalesced both sides.
// Block per (v,y). Block 0 threads 0-7 additionally run the pose prep.
// ---------------------------------------------------------------------------
__global__ void __launch_bounds__(256)
transpose_feats_kernel(const float* __restrict__ feats,
                       const float* __restrict__ poses,
                       const float* __restrict__ Kc,
                       const float* __restrict__ Kd) {
    __shared__ float tile[CCH * 81];          // 81-pad: conflict-free phase 2
    const int bid = blockIdx.x;               // 0..479
    const int v = bid / FHH;
    const int y = bid % FHH;
    const int tid = threadIdx.x;

    for (int i = tid; i < CCH * FWW; i += 256) {
        int c = i / FWW, x = i % FWW;
        tile[c * 81 + x] = feats[((v * CCH + c) * FHH + y) * FWW + x];
    }
    __syncthreads();

    float* ob = g_feats_t + ((size_t)v * FHH * FWW + (size_t)y * FWW) * CP;
    for (int i = tid; i < FWW * CP; i += 256) {
        int x = i / CP, c = i % CP;
        ob[i] = (c < CCH) ? tile[c * 81 + x] : 0.0f;
    }

    if (bid == 0 && tid < BV)
        prep_view(tid, poses, Kc, Kd);
}

// Frozen rounding recipe (matches XLA): unfused mul-then-reduce dots.
__device__ __forceinline__ float dot4_mr(const float* r, float x, float y,
                                         float z, float w) {
    float t0 = __fmul_rn(r[0], x);
    float t1 = __fmul_rn(r[1], y);
    float t2 = __fmul_rn(r[2], z);
    float t3 = __fmul_rn(r[3], w);
    return __fadd_rn(__fadd_rn(__fadd_rn(t0, t1), t2), t3);
}
__device__ __forceinline__ float dot3_mr(const float* r, float x, float y,
                                         float z) {
    float t0 = __fmul_rn(r[0], x);
    float t1 = __fmul_rn(r[1], y);
    float t2 = __fmul_rn(r[2], z);
    return __fadd_rn(__fadd_rn(t0, t1), t2);
}

// ---------------------------------------------------------------------------
// Fuse: one WARP per point. Lanes 0-7: per-view projection (frozen math).
// Gather: lanes 0-23 = {2 corners} x {12 float4 channel slots}, 2 passes.
// ---------------------------------------------------------------------------
__global__ void __launch_bounds__(256)
fuse_kernel(const float* __restrict__ coords,
            const float* __restrict__ depth,
            float* __restrict__ out) {
    const unsigned FULL = 0xffffffffu;
    const int warp = threadIdx.x >> 5;
    const int lane = threadIdx.x & 31;
    const int n = blockIdx.x * WPB + warp;    // grid*WPB == NPTS exactly

    const float px = coords[n * 3 + 0];
    const float py = coords[n * 3 + 1];
    const float pz = coords[n * 3 + 2];

    // ---- projection for view (lane & 7) — EXACT frozen recipe ----
    const int v = lane & 7;
    const float* P = g_proj[v];
    float cam0 = dot4_mr(P + 0, px, py, pz, 1.0f);
    float cam1 = dot4_mr(P + 4, px, py, pz, 1.0f);
    float cam2 = dot4_mr(P + 8, px, py, pz, 1.0f);
    float z  = cam2;
    float zs = (fabsf(z) > 1e-6f) ? z : 1e-6f;
    float recip = __fdiv_rn(1.0f, zs);

    float uc = __fmul_rn(dot3_mr(P + 12, cam0, cam1, cam2), recip);
    float vc = __fmul_rn(dot3_mr(P + 15, cam0, cam1, cam2), recip);
    float ud = __fmul_rn(dot3_mr(P + 18, cam0, cam1, cam2), recip);
    float vd = __fmul_rn(dot3_mr(P + 21, cam0, cam1, cam2), recip);

    bool valid_c = (uc >= 0.0f) & (uc <= (float)(FWW - 1)) &
                   (vc >= 0.0f) & (vc <= (float)(FHH - 1));
    bool valid_d = (ud >= 0.0f) & (ud <= (float)(DWW - 1)) &
                   (vd >= 0.0f) & (vd <= (float)(DHH - 1));

    int xi = (int)fminf(fmaxf(rintf(ud), 0.0f), (float)(DWW - 1));
    int yi = (int)fminf(fmaxf(rintf(vd), 0.0f), (float)(DHH - 1));
    float ds = __ldg(&depth[(v * DHH + yi) * DWW + xi]);

    bool valid = valid_c & valid_d & (z > 0.0f) & (ds > 0.0f);
    float dist = __fmul_rn(fabsf(__fsub_rn(z, ds)), 16.0f);
    float w  = valid ? expf(-__fmul_rn(dist, dist)) : 0.0f;
    float vc01 = valid ? 1.0f : 0.0f;

    // ---- gather phase ----
    const int corner = lane / 12;             // 0,1 (lanes>=24 idle)
    const int c4     = lane % 12;
    const bool ld_act = (lane < 24);
    float4 acc = make_float4(0.0f, 0.0f, 0.0f, 0.0f);
    float wsum = 0.0f, cnt = 0.0f;

#pragma unroll 1
    for (int vv = 0; vv < BV; vv++) {
        float wv = __shfl_sync(FULL, w, vv);
        wsum += wv;
        cnt  += __shfl_sync(FULL, vc01, vv);
        if (wv == 0.0f) continue;             // warp-uniform skip

        float ucv = __shfl_sync(FULL, uc, vv);
        float vcv = __shfl_sync(FULL, vc, vv);
        float ucl = fminf(fmaxf(ucv, 0.0f), (float)(FWW - 1));
        float vcl = fminf(fmaxf(vcv, 0.0f), (float)(FHH - 1));
        float x0f = floorf(ucl), y0f = floorf(vcl);
        int x0 = (int)x0f, y0 = (int)y0f;
        int x1 = min(x0 + 1, FWW - 1);
        int y1 = min(y0 + 1, FHH - 1);
        float wx = ucl - x0f, wy = vcl - y0f;
        float w00 = wv * (1.0f - wy) * (1.0f - wx);
        float w01 = wv * (1.0f - wy) * wx;
        float w10 = wv * wy * (1.0f - wx);
        float w11 = wv * wy * wx;

        if (ld_act) {
            const float* fb = g_feats_t + (size_t)vv * (FHH * FWW * CP);
            int xA = corner ? x1 : x0;
            float wA = corner ? w01 : w00;
            float wB = corner ? w11 : w10;
            const float4* pA = (const float4*)&fb[(y0 * FWW + xA) * CP + c4 * 4];
            const float4* pB = (const float4*)&fb[(y1 * FWW + xA) * CP + c4 * 4];
            float4 fA = __ldg(pA);
            float4 fB = __ldg(pB);
            acc.x += wA * fA.x + wB * fB.x;
            acc.y += wA * fA.y + wB * fB.y;
            acc.z += wA * fA.z + wB * fB.z;
            acc.w += wA * fA.w + wB * fB.w;
        }
    }

    // fold the two corner-halves: lanes 0-11 += lanes 12-23
    acc.x += __shfl_down_sync(FULL, acc.x, 12);
    acc.y += __shfl_down_sync(FULL, acc.y, 12);
    acc.z += __shfl_down_sync(FULL, acc.z, 12);
    acc.w += __shfl_down_sync(FULL, acc.w, 12);

    __shared__ float sred[WPB][52];
    if (lane < 12) {
        sred[warp][c4 * 4 + 0] = acc.x;
        sred[warp][c4 * 4 + 1] = acc.y;
        sred[warp][c4 * 4 + 2] = acc.z;
        sred[warp][c4 * 4 + 3] = acc.w;
    }
    __syncwarp();
    if (lane == 0) {
        sred[warp][47] = wsum;   // overwrite padding channel
        sred[warp][48] = cnt;
    }
    __syncthreads();

    // coalesced block-wide store: out layout density(47,N) | wsum(N) | cnt(N)
    const int base_n = blockIdx.x * WPB;
    for (int t = threadIdx.x; t < 49 * WPB; t += 256) {
        int c = t >> 3, j = t & 7;
        out[(size_t)c * NPTS + base_n + j] = sred[j][c];
    }
}

// ---------------------------------------------------------------------------
extern "C" void kernel_launch(void* const* d_in, const int* in_sizes, int n_in,
                              void* d_out, int out_size) {
    const float* img_feats  = (const float*)d_in[0];   // (1,8,47,60,80)
    const float* pred_depth = (const float*)d_in[1];   // (1,8,240,320)
    const float* poses      = (const float*)d_in[2];   // (1,8,4,4)
    const float* K_color    = (const float*)d_in[3];   // (1,8,3,3)
    const float* K_depth    = (const float*)d_in[4];   // (1,8,3,3)
    const float* coords     = (const float*)d_in[5];   // (1,150000,3)
    float* out = (float*)d_out;

    transpose_feats_kernel<<<BV * FHH, 256>>>(img_feats, poses, K_color, K_depth);
    fuse_kernel<<<NPTS / WPB, 256>>>(coords, pred_depth, out);
}